// round 3
// baseline (speedup 1.0000x reference)
#include <cuda_runtime.h>

// ---------------- problem constants ----------------
#define N_NODES 50000
#define N_EDGES 600000
#define IN_CH   16
#define ED      8
#define HID     128
#define HEADS   4
#define CH      32      // HID / HEADS
#define EMB_D   64      // HID/2
#define FEAT    64      // HID - EMB
#define SLOPE   0.2f

// ---------------- scratch (device globals; no allocation allowed) ----------------
__device__ float g_z  [N_NODES * HID];   // features in
__device__ float g_z2 [N_NODES * HID];   // features out of layer 1
__device__ float g_xl [N_NODES * HID];   // source-side projection
__device__ float g_xr [N_NODES * HID];   // target-side projection
__device__ float g_agg[N_NODES * HID];   // unnormalized attention-weighted aggregation
__device__ float g_den[N_NODES * HEADS]; // softmax denominator per (dst, head)

// vector reduction: 1 RED.128 instead of 4 RED.32 (PTX ISA 8.1+, sm_90+)
__device__ __forceinline__ void red_add_v4(float* addr, float4 v) {
    asm volatile("red.global.add.v4.f32 [%0], {%1,%2,%3,%4};"
                 :: "l"(addr), "f"(v.x), "f"(v.y), "f"(v.z), "f"(v.w)
                 : "memory");
}

// ---------------- kernels ----------------

// z[n, 0:64] = relu(x[n,:] @ W_in + b_in);  z[n, 64:128] = emb[node_idx[n]]
__global__ void node_init_kernel(const float* __restrict__ x,
                                 const int*   __restrict__ node_idx,
                                 const float* __restrict__ emb,
                                 const float* __restrict__ W_in,
                                 const float* __restrict__ b_in) {
    int n = blockIdx.x;
    int t = threadIdx.x;  // 128 threads
    __shared__ float xs[IN_CH];
    if (t < IN_CH) xs[t] = x[n * IN_CH + t];
    __syncthreads();
    if (t < FEAT) {
        float acc = b_in[t];
#pragma unroll
        for (int k = 0; k < IN_CH; k++) acc = fmaf(xs[k], W_in[k * FEAT + t], acc);
        g_z[n * HID + t] = fmaxf(acc, 0.f);
    } else {
        int j = t - FEAT;
        int e = node_idx[n];
        g_z[n * HID + FEAT + j] = emb[e * EMB_D + j];
    }
}

// Out[r, c] = sum_k A[r,k] * W[k,c] + bias[c].  A:[nrows,128], W:[128,128].
// 64x64 tile, 256 threads, 4x4 micro-tile per thread.
__global__ void gemm128_kernel(const float* __restrict__ A,
                               const float* __restrict__ W,
                               const float* __restrict__ bias,
                               float* __restrict__ Out, int nrows) {
    __shared__ float As[16][64];
    __shared__ float Bs[16][64];
    int tid = threadIdx.x;
    int ty = tid >> 4, tx = tid & 15;
    int rowBase = blockIdx.x * 64;
    int colBase = blockIdx.y * 64;
    float acc[4][4] = {};

    int lr  = tid >> 2;          // A-tile row 0..63
    int lc  = (tid & 3) * 4;     // A-tile col group (of 16)
    int bkr = tid >> 4;          // B-tile row 0..15
    int bc  = (tid & 15) * 4;    // B-tile col 0..60

    for (int kt = 0; kt < 128; kt += 16) {
        float4 av = make_float4(0.f, 0.f, 0.f, 0.f);
        int ar = rowBase + lr;
        if (ar < nrows) av = *(const float4*)(A + ar * 128 + kt + lc);
        As[lc + 0][lr] = av.x; As[lc + 1][lr] = av.y;
        As[lc + 2][lr] = av.z; As[lc + 3][lr] = av.w;
        float4 bv = *(const float4*)(W + (kt + bkr) * 128 + colBase + bc);
        *(float4*)(&Bs[bkr][bc]) = bv;
        __syncthreads();
#pragma unroll
        for (int k = 0; k < 16; k++) {
            float4 a = *(const float4*)(&As[k][ty * 4]);
            float4 b = *(const float4*)(&Bs[k][tx * 4]);
            float ai[4] = {a.x, a.y, a.z, a.w};
            float bj[4] = {b.x, b.y, b.z, b.w};
#pragma unroll
            for (int i = 0; i < 4; i++)
#pragma unroll
                for (int j = 0; j < 4; j++)
                    acc[i][j] = fmaf(ai[i], bj[j], acc[i][j]);
        }
        __syncthreads();
    }
#pragma unroll
    for (int i = 0; i < 4; i++) {
        int r = rowBase + ty * 4 + i;
        if (r >= nrows) continue;
#pragma unroll
        for (int j = 0; j < 4; j++) {
            int c = colBase + tx * 4 + j;
            Out[r * 128 + c] = acc[i][j] + bias[c];
        }
    }
}

// zero g_agg and g_den (float4 stores)
__global__ void zero_kernel() {
    int i = blockIdx.x * 256 + threadIdx.x;
    float4 z4 = make_float4(0.f, 0.f, 0.f, 0.f);
    if (i < N_NODES * HID / 4)   ((float4*)g_agg)[i] = z4;
    if (i < N_NODES * HEADS / 4) ((float4*)g_den)[i] = z4;
}

// FUSED edge pass. One warp per edge; lane owns channels [4*lane, 4*lane+4),
// so head(lane) = lane>>3 and every gather/scatter is a 16B vector op.
//   logit_h = att_h . leakyrelu(xl[src]+xr[dst]+ee)   (3-step segmented reduce)
//   ex_h    = exp(logit_h)        (max-shift skipped: softmax shift-invariant,
//                                  logits are O(1) for these scales)
//   den[dst,h] += ex_h            (scalar atomic, 1 lane per head group)
//   agg[dst,:] += ex_h * xl[src,:] (red.global.add.v4.f32 per lane)
// Normalization by den happens in post_ln_kernel (algebraically identical).
__global__ void edge_fused_kernel(const int*   __restrict__ ei,
                                  const float* __restrict__ ea,
                                  const float* __restrict__ We,
                                  const float* __restrict__ be,
                                  const float* __restrict__ att) {
    __shared__ float4 sWe[ED][32];   // We[k, 4*lane..4*lane+3]
    __shared__ float4 sbe[32];
    __shared__ float4 satt[32];
    int t = threadIdx.x;  // 256 = ED*32 exactly
    sWe[t >> 5][t & 31] = ((const float4*)We)[t];
    if (t < 32) { sbe[t] = ((const float4*)be)[t]; satt[t] = ((const float4*)att)[t]; }
    __syncthreads();

    int e = blockIdx.x * 8 + (t >> 5);
    if (e >= N_EDGES) return;
    int lane = t & 31;
    int src = ei[e];
    int dst = ei[N_EDGES + e];

    const float4* eap = (const float4*)(ea + e * ED);
    float4 ea0 = eap[0], ea1 = eap[1];
    float eav[ED] = {ea0.x, ea0.y, ea0.z, ea0.w, ea1.x, ea1.y, ea1.z, ea1.w};

    float4 xl4 = ((const float4*)(g_xl + src * HID))[lane];
    float4 xr4 = ((const float4*)(g_xr + dst * HID))[lane];
    float4 b4  = sbe[lane];

    float4 v;
    v.x = xl4.x + xr4.x + b4.x;
    v.y = xl4.y + xr4.y + b4.y;
    v.z = xl4.z + xr4.z + b4.z;
    v.w = xl4.w + xr4.w + b4.w;
#pragma unroll
    for (int k = 0; k < ED; k++) {
        float4 w = sWe[k][lane];
        v.x = fmaf(eav[k], w.x, v.x);
        v.y = fmaf(eav[k], w.y, v.y);
        v.z = fmaf(eav[k], w.z, v.z);
        v.w = fmaf(eav[k], w.w, v.w);
    }
    // LeakyReLU
    v.x = (v.x > 0.f) ? v.x : SLOPE * v.x;
    v.y = (v.y > 0.f) ? v.y : SLOPE * v.y;
    v.z = (v.z > 0.f) ? v.z : SLOPE * v.z;
    v.w = (v.w > 0.f) ? v.w : SLOPE * v.w;

    float4 a4 = satt[lane];
    float part = v.x * a4.x + v.y * a4.y + v.z * a4.z + v.w * a4.w;
    // segmented butterfly over the 8 lanes of this head group
    part += __shfl_xor_sync(0xffffffffu, part, 1);
    part += __shfl_xor_sync(0xffffffffu, part, 2);
    part += __shfl_xor_sync(0xffffffffu, part, 4);
    float ex = __expf(part);

    if ((lane & 7) == 0)
        atomicAdd(&g_den[dst * HEADS + (lane >> 3)], ex);

    float4 contrib = make_float4(xl4.x * ex, xl4.y * ex, xl4.z * ex, xl4.w * ex);
    red_add_v4(g_agg + dst * HID + lane * 4, contrib);
}

// zout = LayerNorm(zin + relu(agg/den + bo)) * g + beta.  One warp per node.
// den==0 (isolated node) -> contribution is exactly 0, matching reference.
__global__ void post_ln_kernel(const float* __restrict__ zin,
                               const float* __restrict__ bo,
                               const float* __restrict__ gamma,
                               const float* __restrict__ beta,
                               float* __restrict__ zout) {
    int t = threadIdx.x;
    int n = blockIdx.x * 8 + (t >> 5);
    if (n >= N_NODES) return;
    int lane = t & 31;

    float d   = g_den[n * HEADS + (lane >> 3)];
    float inv = (d > 0.f) ? (1.f / d) : 0.f;

    float4 ag = ((const float4*)(g_agg + n * HID))[lane];
    float4 b4 = ((const float4*)bo)[lane];
    float4 zi = ((const float4*)(zin + n * HID))[lane];

    float4 y;
    y.x = zi.x + fmaxf(ag.x * inv + b4.x, 0.f);
    y.y = zi.y + fmaxf(ag.y * inv + b4.y, 0.f);
    y.z = zi.z + fmaxf(ag.z * inv + b4.z, 0.f);
    y.w = zi.w + fmaxf(ag.w * inv + b4.w, 0.f);

    float s  = y.x + y.y + y.z + y.w;
    float ss = y.x * y.x + y.y * y.y + y.z * y.z + y.w * y.w;
#pragma unroll
    for (int off = 16; off; off >>= 1) {
        s  += __shfl_xor_sync(0xffffffffu, s,  off);
        ss += __shfl_xor_sync(0xffffffffu, ss, off);
    }
    float mu  = s * (1.f / 128.f);
    float var = ss * (1.f / 128.f) - mu * mu;
    float r   = rsqrtf(var + 1e-5f);

    float4 g4  = ((const float4*)gamma)[lane];
    float4 be4 = ((const float4*)beta)[lane];
    float4 o;
    o.x = (y.x - mu) * r * g4.x + be4.x;
    o.y = (y.y - mu) * r * g4.y + be4.y;
    o.z = (y.z - mu) * r * g4.z + be4.z;
    o.w = (y.w - mu) * r * g4.w + be4.w;
    ((float4*)(zout + n * HID))[lane] = o;
}

// out[n] = z[n,:] @ W_out + b_out.  One warp per node.
__global__ void head_kernel(const float* __restrict__ z,
                            const float* __restrict__ W_out,
                            const float* __restrict__ b_out,
                            float* __restrict__ out) {
    int t = threadIdx.x;
    int n = blockIdx.x * 8 + (t >> 5);
    if (n >= N_NODES) return;
    int lane = t & 31;
    float4 zv = ((const float4*)(z + n * HID))[lane];
    float4 wv = ((const float4*)W_out)[lane];
    float s = zv.x * wv.x + zv.y * wv.y + zv.z * wv.z + zv.w * wv.w;
#pragma unroll
    for (int off = 16; off; off >>= 1)
        s += __shfl_xor_sync(0xffffffffu, s, off);
    if (lane == 0) out[n] = s + b_out[0];
}

// ---------------- launch ----------------
extern "C" void kernel_launch(void* const* d_in, const int* in_sizes, int n_in,
                              void* d_out, int out_size) {
    const float* x          = (const float*)d_in[0];
    const int*   node_idx   = (const int*)  d_in[1];
    const int*   edge_index = (const int*)  d_in[2];
    const float* edge_attr  = (const float*)d_in[3];
    const float* emb        = (const float*)d_in[4];
    const float* W_in       = (const float*)d_in[5];
    const float* b_in       = (const float*)d_in[6];
    const float* Wl1 = (const float*)d_in[7],  *bl1 = (const float*)d_in[8];
    const float* Wr1 = (const float*)d_in[9],  *br1 = (const float*)d_in[10];
    const float* We1 = (const float*)d_in[11], *be1 = (const float*)d_in[12];
    const float* att1= (const float*)d_in[13], *bo1 = (const float*)d_in[14];
    const float* Wl2 = (const float*)d_in[15], *bl2 = (const float*)d_in[16];
    const float* Wr2 = (const float*)d_in[17], *br2 = (const float*)d_in[18];
    const float* We2 = (const float*)d_in[19], *be2 = (const float*)d_in[20];
    const float* att2= (const float*)d_in[21], *bo2 = (const float*)d_in[22];
    const float* g1   = (const float*)d_in[23], *beta1 = (const float*)d_in[24];
    const float* g2   = (const float*)d_in[25], *beta2 = (const float*)d_in[26];
    const float* W_out= (const float*)d_in[27], *b_out = (const float*)d_in[28];
    float* out = (float*)d_out;

    // scratch pointers for kernels that take buffers as args
    float *pz = nullptr, *pz2 = nullptr, *pxl = nullptr, *pxr = nullptr;
    cudaGetSymbolAddress((void**)&pz,  g_z);
    cudaGetSymbolAddress((void**)&pz2, g_z2);
    cudaGetSymbolAddress((void**)&pxl, g_xl);
    cudaGetSymbolAddress((void**)&pxr, g_xr);

    const int GEMM_GX = (N_NODES + 63) / 64;   // 782
    const dim3 ggrid(GEMM_GX, 2);
    const int EBLK = (N_EDGES + 7) / 8;        // 75000
    const int NBLK = (N_NODES + 7) / 8;        // 6250
    const int ZBLK = (N_NODES * HID / 4 + 255) / 256;

    node_init_kernel<<<N_NODES, 128>>>(x, node_idx, emb, W_in, b_in);

    // ---- layer 1 (z -> z2) ----
    gemm128_kernel<<<ggrid, 256>>>(pz, Wl1, bl1, pxl, N_NODES);
    gemm128_kernel<<<ggrid, 256>>>(pz, Wr1, br1, pxr, N_NODES);
    zero_kernel<<<ZBLK, 256>>>();
    edge_fused_kernel<<<EBLK, 256>>>(edge_index, edge_attr, We1, be1, att1);
    post_ln_kernel<<<NBLK, 256>>>(pz, bo1, g1, beta1, pz2);

    // ---- layer 2 (z2 -> z) ----
    gemm128_kernel<<<ggrid, 256>>>(pz2, Wl2, bl2, pxl, N_NODES);
    gemm128_kernel<<<ggrid, 256>>>(pz2, Wr2, br2, pxr, N_NODES);
    zero_kernel<<<ZBLK, 256>>>();
    edge_fused_kernel<<<EBLK, 256>>>(edge_index, edge_attr, We2, be2, att2);
    post_ln_kernel<<<NBLK, 256>>>(pz2, bo2, g2, beta2, pz);

    head_kernel<<<NBLK, 256>>>(pz, W_out, b_out, out);
}

// round 8
// speedup vs baseline: 1.0886x; 1.0886x over previous
#include <cuda_runtime.h>

// ---------------- problem constants ----------------
#define N_NODES 50000
#define N_EDGES 600000
#define IN_CH   16
#define ED      8
#define HID     128
#define HEADS   4
#define CH      32      // HID / HEADS
#define EMB_D   64      // HID/2
#define FEAT    64      // HID - EMB
#define SLOPE   0.2f

// ---------------- scratch (device globals; no allocation allowed) ----------------
__device__ float g_z  [N_NODES * HID];   // features in
__device__ float g_z2 [N_NODES * HID];   // features out of layer 1
__device__ float g_xl [N_NODES * HID];   // source-side projection
__device__ float g_xr [N_NODES * HID];   // target-side projection
__device__ float g_agg[N_NODES * HID];   // unnormalized attention-weighted aggregation
__device__ float g_den[N_NODES * HEADS]; // softmax denominator per (dst, head)

// vector reduction: 1 RED.128 instead of 4 RED.32 (PTX ISA 8.1+, sm_90+)
__device__ __forceinline__ void red_add_v4(float* addr, float4 v) {
    asm volatile("red.global.add.v4.f32 [%0], {%1,%2,%3,%4};"
                 :: "l"(addr), "f"(v.x), "f"(v.y), "f"(v.z), "f"(v.w)
                 : "memory");
}

// ---------------- kernels ----------------

// z[n, 0:64] = relu(x[n,:] @ W_in + b_in);  z[n, 64:128] = emb[node_idx[n]]
// Also zeroes g_agg[n,:] and g_den[n,:] (block n owns node n; runs at the top
// of every launch, so replay-determinism is preserved).
__global__ void node_init_kernel(const float* __restrict__ x,
                                 const int*   __restrict__ node_idx,
                                 const float* __restrict__ emb,
                                 const float* __restrict__ W_in,
                                 const float* __restrict__ b_in) {
    int n = blockIdx.x;
    int t = threadIdx.x;  // 128 threads
    __shared__ float xs[IN_CH];
    if (t < IN_CH) xs[t] = x[n * IN_CH + t];

    // zero scratch for this node
    float4 z4 = make_float4(0.f, 0.f, 0.f, 0.f);
    if (t < 32)       ((float4*)(g_agg + (size_t)n * HID))[t] = z4;
    else if (t == 32) ((float4*)(g_den + (size_t)n * HEADS))[0] = z4;

    __syncthreads();
    if (t < FEAT) {
        float acc = b_in[t];
#pragma unroll
        for (int k = 0; k < IN_CH; k++) acc = fmaf(xs[k], W_in[k * FEAT + t], acc);
        g_z[n * HID + t] = fmaxf(acc, 0.f);
    } else {
        int j = t - FEAT;
        int e = node_idx[n];
        g_z[n * HID + FEAT + j] = emb[e * EMB_D + j];
    }
}

// DUAL GEMM: O1 = A@W1 + b1, O2 = A@W2 + b2 in one pass over A.
// A:[nrows,128], W:[128,128]. Both weights resident in dynamic smem (128 KB),
// A streamed in 8-wide k slices. 128-row tile, 512 threads, 8x4 microtile per
// output matrix per thread (64 accumulators -> ~100 regs, no spill risk).
// Per thread-k: 64 FMA vs 4 LDS.128 (A reads are warp-broadcast; B reads are
// 512B-contiguous per warp -> conflict-free). Decisively FMA-bound.
#define SA_STRIDE 132   // pad: kp-group offset 4*132 % 32banks = 16 -> store conflict-free
__global__ void __launch_bounds__(512, 1)
gemm_dual_kernel(const float* __restrict__ A,
                 const float* __restrict__ W1, const float* __restrict__ b1,
                 const float* __restrict__ W2, const float* __restrict__ b2,
                 float* __restrict__ O1, float* __restrict__ O2, int nrows) {
    extern __shared__ float sm[];
    float* sW1 = sm;                    // [128][128] k-major
    float* sW2 = sm + 128 * 128;
    float* sA  = sm + 2 * 128 * 128;    // [8][SA_STRIDE], sA[k][row]

    int tid = threadIdx.x;
    // cooperative weight load: 4096 float4 per W, 8 iters per thread per W
    for (int i = tid; i < 128 * 128 / 4; i += 512) {
        ((float4*)sW1)[i] = ((const float4*)W1)[i];
        ((float4*)sW2)[i] = ((const float4*)W2)[i];
    }

    int tx = tid & 31, ty = tid >> 5;          // 32 x 16 thread grid
    int rowBase = blockIdx.x * 128;
    int r0 = ty * 8;                           // 8 rows per thread
    int c0 = tx * 4;                           // 4 cols per matrix

    // A-tile loader: threads 0..255 -> (row = tid>>1, kpart = (tid&1)*4)
    int lrow = tid >> 1;
    int lkp  = (tid & 1) * 4;
    bool loader = tid < 256;
    int garow = rowBase + lrow;
    bool rowok = loader && garow < nrows;
    const float* Arow = A + (size_t)garow * 128;

    float acc1[8][4] = {};
    float acc2[8][4] = {};

    float4 pref = make_float4(0.f, 0.f, 0.f, 0.f);
    if (rowok) pref = *(const float4*)(Arow + lkp);

    __syncthreads();   // weights + first A-slice ordering

    for (int kt = 0; kt < 128; kt += 8) {
        if (loader) {
            sA[(lkp + 0) * SA_STRIDE + lrow] = pref.x;
            sA[(lkp + 1) * SA_STRIDE + lrow] = pref.y;
            sA[(lkp + 2) * SA_STRIDE + lrow] = pref.z;
            sA[(lkp + 3) * SA_STRIDE + lrow] = pref.w;
        }
        __syncthreads();
        if (kt + 8 < 128 && rowok)
            pref = *(const float4*)(Arow + kt + 8 + lkp);

#pragma unroll
        for (int k = 0; k < 8; k++) {
            float a[8];
            *(float4*)(a + 0) = *(const float4*)&sA[k * SA_STRIDE + r0 + 0];
            *(float4*)(a + 4) = *(const float4*)&sA[k * SA_STRIDE + r0 + 4];
            float bb1[4], bb2[4];
            *(float4*)bb1 = *(const float4*)(sW1 + (kt + k) * 128 + c0);
            *(float4*)bb2 = *(const float4*)(sW2 + (kt + k) * 128 + c0);
#pragma unroll
            for (int i = 0; i < 8; i++) {
#pragma unroll
                for (int j = 0; j < 4; j++) {
                    acc1[i][j] = fmaf(a[i], bb1[j], acc1[i][j]);
                    acc2[i][j] = fmaf(a[i], bb2[j], acc2[i][j]);
                }
            }
        }
        __syncthreads();
    }

    // epilogue
    float4 bv1 = *(const float4*)(b1 + c0);
    float4 bv2 = *(const float4*)(b2 + c0);
#pragma unroll
    for (int i = 0; i < 8; i++) {
        int r = rowBase + r0 + i;
        if (r >= nrows) break;
        float4 o;
        o.x = acc1[i][0] + bv1.x; o.y = acc1[i][1] + bv1.y;
        o.z = acc1[i][2] + bv1.z; o.w = acc1[i][3] + bv1.w;
        *(float4*)(O1 + (size_t)r * 128 + c0) = o;
        o.x = acc2[i][0] + bv2.x; o.y = acc2[i][1] + bv2.y;
        o.z = acc2[i][2] + bv2.z; o.w = acc2[i][3] + bv2.w;
        *(float4*)(O2 + (size_t)r * 128 + c0) = o;
    }
}
#define GEMM_SMEM ((2 * 128 * 128 + 8 * SA_STRIDE) * (int)sizeof(float))

// FUSED edge pass, GRID-STRIDE (fixed 1184-block grid -> smem preload happens
// 1184x, not 75000x: saves ~375 MB of redundant L2 reads per layer).
// One warp per edge per iteration; lane owns channels [4*lane, 4*lane+4):
//   logit_h = att_h . leakyrelu(xl[src]+xr[dst]+ee)   (3-step segmented reduce)
//   ex_h    = exp(logit_h)        (max-shift skipped: softmax shift-invariant,
//                                  logits are O(1) for these scales)
//   den[dst,h] += ex_h            (scalar atomic, 1 lane per head group)
//   agg[dst,:] += ex_h * xl[src,:] (red.global.add.v4.f32 per lane)
// Normalization by den happens in the post-LN kernels (algebraically identical).
#define EDGE_BLOCKS 1184   // 8 per SM
__global__ void edge_fused_kernel(const int*   __restrict__ ei,
                                  const float* __restrict__ ea,
                                  const float* __restrict__ We,
                                  const float* __restrict__ be,
                                  const float* __restrict__ att) {
    __shared__ float4 sWe[ED][32];   // We[k, 4*lane..4*lane+3]
    __shared__ float4 sbe[32];
    __shared__ float4 satt[32];
    int t = threadIdx.x;  // 256 = ED*32 exactly
    sWe[t >> 5][t & 31] = ((const float4*)We)[t];
    if (t < 32) { sbe[t] = ((const float4*)be)[t]; satt[t] = ((const float4*)att)[t]; }
    __syncthreads();

    int lane = t & 31;
    int wid  = t >> 5;
    float4 b4 = sbe[lane];
    float4 a4 = satt[lane];

    for (int e = blockIdx.x * 8 + wid; e < N_EDGES; e += EDGE_BLOCKS * 8) {
        int src = ei[e];
        int dst = ei[N_EDGES + e];

        const float4* eap = (const float4*)(ea + (size_t)e * ED);
        float4 ea0 = eap[0], ea1 = eap[1];
        float eav[ED] = {ea0.x, ea0.y, ea0.z, ea0.w, ea1.x, ea1.y, ea1.z, ea1.w};

        float4 xl4 = ((const float4*)(g_xl + (size_t)src * HID))[lane];
        float4 xr4 = ((const float4*)(g_xr + (size_t)dst * HID))[lane];

        float4 v;
        v.x = xl4.x + xr4.x + b4.x;
        v.y = xl4.y + xr4.y + b4.y;
        v.z = xl4.z + xr4.z + b4.z;
        v.w = xl4.w + xr4.w + b4.w;
#pragma unroll
        for (int k = 0; k < ED; k++) {
            float4 w = sWe[k][lane];
            v.x = fmaf(eav[k], w.x, v.x);
            v.y = fmaf(eav[k], w.y, v.y);
            v.z = fmaf(eav[k], w.z, v.z);
            v.w = fmaf(eav[k], w.w, v.w);
        }
        // LeakyReLU
        v.x = (v.x > 0.f) ? v.x : SLOPE * v.x;
        v.y = (v.y > 0.f) ? v.y : SLOPE * v.y;
        v.z = (v.z > 0.f) ? v.z : SLOPE * v.z;
        v.w = (v.w > 0.f) ? v.w : SLOPE * v.w;

        float part = v.x * a4.x + v.y * a4.y + v.z * a4.z + v.w * a4.w;
        // segmented butterfly over the 8 lanes of this head group
        part += __shfl_xor_sync(0xffffffffu, part, 1);
        part += __shfl_xor_sync(0xffffffffu, part, 2);
        part += __shfl_xor_sync(0xffffffffu, part, 4);
        float ex = __expf(part);

        if ((lane & 7) == 0)
            atomicAdd(&g_den[dst * HEADS + (lane >> 3)], ex);

        float4 contrib = make_float4(xl4.x * ex, xl4.y * ex, xl4.z * ex, xl4.w * ex);
        red_add_v4(g_agg + (size_t)dst * HID + lane * 4, contrib);
    }
}

// Shared LN body: y = LN(zin + relu(agg/den + bo)) * g + beta, in registers.
// den==0 (isolated node) -> contribution 0, matching reference.
// If ZERO_SCRATCH, re-zeros the consumed agg/den words (same thread owns them).
template <bool ZERO_SCRATCH>
__device__ __forceinline__ float4 ln_body(int n, int lane,
                                          const float* __restrict__ zin,
                                          const float* __restrict__ bo,
                                          const float* __restrict__ gamma,
                                          const float* __restrict__ beta) {
    float d   = g_den[n * HEADS + (lane >> 3)];
    float inv = (d > 0.f) ? (1.f / d) : 0.f;

    float4 ag = ((const float4*)(g_agg + (size_t)n * HID))[lane];
    float4 b4 = ((const float4*)bo)[lane];
    float4 zi = ((const float4*)(zin + (size_t)n * HID))[lane];

    if (ZERO_SCRATCH) {
        ((float4*)(g_agg + (size_t)n * HID))[lane] = make_float4(0.f, 0.f, 0.f, 0.f);
        if ((lane & 7) == 0) g_den[n * HEADS + (lane >> 3)] = 0.f;
    }

    float4 y;
    y.x = zi.x + fmaxf(ag.x * inv + b4.x, 0.f);
    y.y = zi.y + fmaxf(ag.y * inv + b4.y, 0.f);
    y.z = zi.z + fmaxf(ag.z * inv + b4.z, 0.f);
    y.w = zi.w + fmaxf(ag.w * inv + b4.w, 0.f);

    float s  = y.x + y.y + y.z + y.w;
    float ss = y.x * y.x + y.y * y.y + y.z * y.z + y.w * y.w;
#pragma unroll
    for (int off = 16; off; off >>= 1) {
        s  += __shfl_xor_sync(0xffffffffu, s,  off);
        ss += __shfl_xor_sync(0xffffffffu, ss, off);
    }
    float mu  = s * (1.f / 128.f);
    float var = ss * (1.f / 128.f) - mu * mu;
    float r   = rsqrtf(var + 1e-5f);

    float4 g4  = ((const float4*)gamma)[lane];
    float4 be4 = ((const float4*)beta)[lane];
    float4 o;
    o.x = (y.x - mu) * r * g4.x + be4.x;
    o.y = (y.y - mu) * r * g4.y + be4.y;
    o.z = (y.z - mu) * r * g4.z + be4.z;
    o.w = (y.w - mu) * r * g4.w + be4.w;
    return o;
}

// Layer-1 post-LN: writes z2, re-zeros scratch for layer 2. One warp per node.
__global__ void post_ln1_kernel(const float* __restrict__ zin,
                                const float* __restrict__ bo,
                                const float* __restrict__ gamma,
                                const float* __restrict__ beta,
                                float* __restrict__ zout) {
    int t = threadIdx.x;
    int n = blockIdx.x * 8 + (t >> 5);
    if (n >= N_NODES) return;
    int lane = t & 31;
    float4 o = ln_body<true>(n, lane, zin, bo, gamma, beta);
    ((float4*)(zout + (size_t)n * HID))[lane] = o;
}

// Layer-2 post-LN fused with output head: out[n] = LN(...) . W_out + b_out.
__global__ void post_ln2_head_kernel(const float* __restrict__ zin,
                                     const float* __restrict__ bo,
                                     const float* __restrict__ gamma,
                                     const float* __restrict__ beta,
                                     const float* __restrict__ W_out,
                                     const float* __restrict__ b_out,
                                     float* __restrict__ out) {
    int t = threadIdx.x;
    int n = blockIdx.x * 8 + (t >> 5);
    if (n >= N_NODES) return;
    int lane = t & 31;
    float4 o = ln_body<false>(n, lane, zin, bo, gamma, beta);
    float4 wv = ((const float4*)W_out)[lane];
    float s = o.x * wv.x + o.y * wv.y + o.z * wv.z + o.w * wv.w;
#pragma unroll
    for (int off = 16; off; off >>= 1)
        s += __shfl_xor_sync(0xffffffffu, s, off);
    if (lane == 0) out[n] = s + b_out[0];
}

// ---------------- launch ----------------
extern "C" void kernel_launch(void* const* d_in, const int* in_sizes, int n_in,
                              void* d_out, int out_size) {
    const float* x          = (const float*)d_in[0];
    const int*   node_idx   = (const int*)  d_in[1];
    const int*   edge_index = (const int*)  d_in[2];
    const float* edge_attr  = (const float*)d_in[3];
    const float* emb        = (const float*)d_in[4];
    const float* W_in       = (const float*)d_in[5];
    const float* b_in       = (const float*)d_in[6];
    const float* Wl1 = (const float*)d_in[7],  *bl1 = (const float*)d_in[8];
    const float* Wr1 = (const float*)d_in[9],  *br1 = (const float*)d_in[10];
    const float* We1 = (const float*)d_in[11], *be1 = (const float*)d_in[12];
    const float* att1= (const float*)d_in[13], *bo1 = (const float*)d_in[14];
    const float* Wl2 = (const float*)d_in[15], *bl2 = (const float*)d_in[16];
    const float* Wr2 = (const float*)d_in[17], *br2 = (const float*)d_in[18];
    const float* We2 = (const float*)d_in[19], *be2 = (const float*)d_in[20];
    const float* att2= (const float*)d_in[21], *bo2 = (const float*)d_in[22];
    const float* g1   = (const float*)d_in[23], *beta1 = (const float*)d_in[24];
    const float* g2   = (const float*)d_in[25], *beta2 = (const float*)d_in[26];
    const float* W_out= (const float*)d_in[27], *b_out = (const float*)d_in[28];
    float* out = (float*)d_out;

    // scratch pointers for kernels that take buffers as args
    float *pz = nullptr, *pz2 = nullptr, *pxl = nullptr, *pxr = nullptr;
    cudaGetSymbolAddress((void**)&pz,  g_z);
    cudaGetSymbolAddress((void**)&pz2, g_z2);
    cudaGetSymbolAddress((void**)&pxl, g_xl);
    cudaGetSymbolAddress((void**)&pxr, g_xr);

    // idempotent, unconditional (no static guards allowed)
    cudaFuncSetAttribute(gemm_dual_kernel,
                         cudaFuncAttributeMaxDynamicSharedMemorySize, GEMM_SMEM);

    const int GEMM_GX = (N_NODES + 127) / 128;  // 391
    const int NBLK = (N_NODES + 7) / 8;         // 6250

    // init features + zero all scratch (every launch -> replay-deterministic)
    node_init_kernel<<<N_NODES, 128>>>(x, node_idx, emb, W_in, b_in);

    // ---- layer 1 (z -> z2); post_ln1 re-zeros scratch for layer 2 ----
    gemm_dual_kernel<<<GEMM_GX, 512, GEMM_SMEM>>>(pz, Wl1, bl1, Wr1, br1, pxl, pxr, N_NODES);
    edge_fused_kernel<<<EDGE_BLOCKS, 256>>>(edge_index, edge_attr, We1, be1, att1);
    post_ln1_kernel<<<NBLK, 256>>>(pz, bo1, g1, beta1, pz2);

    // ---- layer 2 (z2 -> out), head fused into post-LN ----
    gemm_dual_kernel<<<GEMM_GX, 512, GEMM_SMEM>>>(pz2, Wl2, bl2, Wr2, br2, pxl, pxr, N_NODES);
    edge_fused_kernel<<<EDGE_BLOCKS, 256>>>(edge_index, edge_attr, We2, be2, att2);
    post_ln2_head_kernel<<<NBLK, 256>>>(pz2, bo2, g2, beta2, W_out, b_out, out);
}